// round 8
// baseline (speedup 1.0000x reference)
#include <cuda_runtime.h>
#include <math.h>
#include <float.h>
#include <limits.h>
#include <stdint.h>

#define B_    4
#define NIN_  4096
#define M_    16384
#define CIN_  256
#define COUT_ 128

#define GB_     16
#define NCELL_  (GB_ * GB_ * GB_)   // 4096
#define GLO_    (-4.0f)
#define GW_     0.5f
#define MARGIN_ 1e-3f

typedef unsigned long long ull;

// ---------------- f32x2 packed helpers ----------------
__device__ __forceinline__ ull pack2(float lo, float hi) {
    ull r; asm("mov.b64 %0,{%1,%2};" : "=l"(r) : "f"(lo), "f"(hi)); return r;
}
__device__ __forceinline__ void unpack2(float& lo, float& hi, ull v) {
    asm("mov.b64 {%0,%1},%2;" : "=f"(lo), "=f"(hi) : "l"(v));
}
__device__ __forceinline__ ull fma2(ull a, ull b, ull c) {
    ull d; asm("fma.rn.f32x2 %0,%1,%2,%3;" : "=l"(d) : "l"(a), "l"(b), "l"(c)); return d;
}

// ---------------- scratch ----------------
__device__ float  g_bufA[B_ * COUT_ * NIN_];
__device__ float  g_bufB[B_ * COUT_ * NIN_];
__device__ float  g_featT[B_ * NIN_ * COUT_];
__device__ float  g_wv[B_ * M_ * 3];
__device__ int    g_iv[B_ * M_ * 3];
__device__ float4 g_spts[B_ * NIN_];          // sorted points (x,y,z,sn)
__device__ int    g_sidx[B_ * NIN_];          // original indices of sorted points
__device__ int    g_cstart[B_ * (NCELL_ + 1)];
__device__ int    g_qord[B_ * M_];            // query ids in cell-sorted order

// ---------------- grid helpers ----------------
__device__ __forceinline__ int binof(float v) {
    int t = (int)floorf((v - GLO_) * 2.0f);
    return min(GB_ - 1, max(0, t));
}
// distance from q to bin b's interval; edge bins extend to +/- inf
__device__ __forceinline__ float axdist(float q, int b) {
    float lo = GLO_ + b * GW_;
    float hi = lo + GW_;
    float d = 0.0f;
    if (b > 0       && q < lo) d = lo - q;
    if (b < GB_ - 1 && q > hi) d = q - hi;
    return d;
}

// ---------------- sort candidates into cells (one block per batch) ----------------
__global__ __launch_bounds__(256) void sortpts_kernel(
    const float* __restrict__ xyzin,
    float4* __restrict__ spts, int* __restrict__ sidx, int* __restrict__ cstart)
{
    __shared__ int cnt[NCELL_];
    __shared__ int base[NCELL_];
    __shared__ int wtot[8];
    const int b = blockIdx.x, tid = threadIdx.x;
    const float* pin = xyzin + (size_t)b * NIN_ * 3;

    for (int i = tid; i < NCELL_; i += 256) cnt[i] = 0;
    __syncthreads();
    for (int j = tid; j < NIN_; j += 256) {
        float x = pin[3 * j], y = pin[3 * j + 1], z = pin[3 * j + 2];
        int c = (binof(x) * GB_ + binof(y)) * GB_ + binof(z);
        atomicAdd(&cnt[c], 1);
    }
    __syncthreads();

    // exclusive prefix sum over cnt[4096] with 256 threads (16 each)
    int o = tid * 16, s = 0;
#pragma unroll
    for (int k = 0; k < 16; k++) s += cnt[o + k];
    int lane = tid & 31, wid = tid >> 5, v = s;
#pragma unroll
    for (int d = 1; d < 32; d <<= 1) {
        int t = __shfl_up_sync(~0u, v, d);
        if (lane >= d) v += t;
    }
    if (lane == 31) wtot[wid] = v;
    __syncthreads();
    int wo = 0;
    for (int w = 0; w < wid; w++) wo += wtot[w];
    int run = wo + v - s;
#pragma unroll
    for (int k = 0; k < 16; k++) { int c = cnt[o + k]; base[o + k] = run; run += c; }
    __syncthreads();

    int* cs = cstart + (size_t)b * (NCELL_ + 1);
    for (int i = tid; i < NCELL_; i += 256) cs[i] = base[i];
    if (tid == 0) cs[NCELL_] = NIN_;
    __syncthreads();

    for (int j = tid; j < NIN_; j += 256) {
        float x = pin[3 * j], y = pin[3 * j + 1], z = pin[3 * j + 2];
        int c = (binof(x) * GB_ + binof(y)) * GB_ + binof(z);
        int pos = atomicAdd(&base[c], 1);
        float sn = __fadd_rn(__fadd_rn(__fmul_rn(x, x), __fmul_rn(y, y)),
                             __fmul_rn(z, z));
        spts[(size_t)b * NIN_ + pos] = make_float4(x, y, z, sn);
        sidx[(size_t)b * NIN_ + pos] = j;
    }
}

// ---------------- sort queries by cell (one block per batch) ----------------
__global__ __launch_bounds__(256) void sortq_kernel(
    const float* __restrict__ xyzout, int* __restrict__ qord)
{
    __shared__ int cnt[NCELL_];
    __shared__ int base[NCELL_];
    __shared__ int wtot[8];
    const int b = blockIdx.x, tid = threadIdx.x;
    const float* qp = xyzout + (size_t)b * M_ * 3;

    for (int i = tid; i < NCELL_; i += 256) cnt[i] = 0;
    __syncthreads();
    for (int j = tid; j < M_; j += 256) {
        float x = qp[3 * j], y = qp[3 * j + 1], z = qp[3 * j + 2];
        int c = (binof(x) * GB_ + binof(y)) * GB_ + binof(z);
        atomicAdd(&cnt[c], 1);
    }
    __syncthreads();

    int o = tid * 16, s = 0;
#pragma unroll
    for (int k = 0; k < 16; k++) s += cnt[o + k];
    int lane = tid & 31, wid = tid >> 5, v = s;
#pragma unroll
    for (int d = 1; d < 32; d <<= 1) {
        int t = __shfl_up_sync(~0u, v, d);
        if (lane >= d) v += t;
    }
    if (lane == 31) wtot[wid] = v;
    __syncthreads();
    int wo = 0;
    for (int w = 0; w < wid; w++) wo += wtot[w];
    int run = wo + v - s;
#pragma unroll
    for (int k = 0; k < 16; k++) { int c = cnt[o + k]; base[o + k] = run; run += c; }
    __syncthreads();

    for (int j = tid; j < M_; j += 256) {
        float x = qp[3 * j], y = qp[3 * j + 1], z = qp[3 * j + 2];
        int c = (binof(x) * GB_ + binof(y)) * GB_ + binof(z);
        int pos = atomicAdd(&base[c], 1);
        qord[(size_t)b * M_ + pos] = j;
    }
}

// ---------------- exact grid 3-NN ----------------
// Selection = 3 smallest under lexicographic (clamped d2, original index):
// identical to jax.lax.top_k stable tie-break, and order-invariant, so cell
// processing order is irrelevant. d2 uses the reference algebra bit-for-bit.
// Cell skip: lb2 >= s2 + MARGIN_ with lb from the cell's (edge-extended)
// rectangle; MARGIN_=1e-3 >> all rounding terms (<2e-5) -> provably safe.
#define SMEM_NN_ (NIN_ * 16 + NIN_ * 4 + (NCELL_ + 1) * 4)

__global__ __launch_bounds__(256) void nn_kernel(
    const float4* __restrict__ spts, const int* __restrict__ sidx,
    const int* __restrict__ cstart, const int* __restrict__ qord,
    const float* __restrict__ xyzout,
    float* __restrict__ wout, int* __restrict__ iout)
{
    extern __shared__ char smem[];
    float4* pts = (float4*)smem;
    int* sid = (int*)(smem + NIN_ * 16);
    int* cst = (int*)(smem + NIN_ * 16 + NIN_ * 4);

    const int b = blockIdx.y, tid = threadIdx.x;
    {
        const float4* gp = spts + (size_t)b * NIN_;
        for (int i = tid; i < NIN_; i += 256) pts[i] = gp[i];
        const int* gs = sidx + (size_t)b * NIN_;
        for (int i = tid; i < NIN_; i += 256) sid[i] = gs[i];
        const int* gc = cstart + (size_t)b * (NCELL_ + 1);
        for (int i = tid; i <= NCELL_; i += 256) cst[i] = gc[i];
    }
    __syncthreads();

    const int m = qord[(size_t)b * M_ + blockIdx.x * 256 + tid];
    const float* q = xyzout + ((size_t)b * M_ + m) * 3;
    const float qx = q[0], qy = q[1], qz = q[2];
    const float qn = __fadd_rn(__fadd_rn(__fmul_rn(qx, qx), __fmul_rn(qy, qy)),
                               __fmul_rn(qz, qz));

    float s0 = FLT_MAX, s1 = FLT_MAX, s2 = FLT_MAX;
    int   i0 = INT_MAX, i1 = INT_MAX, i2 = INT_MAX;

    auto docell = [&](int c) {
        int e = cst[c + 1];
        for (int k = cst[c]; k < e; k++) {
            float4 p = pts[k];
            float dot = __fmaf_rn(qz, p.z, __fmaf_rn(qy, p.y, __fmul_rn(qx, p.x)));
            float t   = __fadd_rn(qn, p.w);
            float d   = __fmaf_rn(-2.0f, dot, t);
            d = (d < 0.0f) ? 1e-7f : d;
            int j = sid[k];
            if (d < s2 || (d == s2 && j < i2)) {
                if (d < s1 || (d == s1 && j < i1)) {
                    s2 = s1; i2 = i1;
                    if (d < s0 || (d == s0 && j < i0)) { s1 = s0; i1 = i0; s0 = d; i0 = j; }
                    else                               { s1 = d;  i1 = j; }
                } else { s2 = d; i2 = j; }
            }
        }
    };

    const int bx0 = binof(qx), by0 = binof(qy), bz0 = binof(qz);

    auto dozrun = [&](int bx, int by, float dxy2) {
        int cb = (bx * GB_ + by) * GB_;
        for (int bz = bz0; bz < GB_; bz++) {
            float dz = axdist(qz, bz);
            float lb = __fmaf_rn(dz, dz, dxy2);
            if (lb >= s2 + MARGIN_) break;
            docell(cb + bz);
        }
        for (int bz = bz0 - 1; bz >= 0; bz--) {
            float dz = axdist(qz, bz);
            float lb = __fmaf_rn(dz, dz, dxy2);
            if (lb >= s2 + MARGIN_) break;
            docell(cb + bz);
        }
    };

    auto docol = [&](int bx, float dx2) {
        for (int by = by0; by < GB_; by++) {
            float dy = axdist(qy, by);
            float dxy2 = __fmaf_rn(dy, dy, dx2);
            if (dxy2 >= s2 + MARGIN_) break;
            dozrun(bx, by, dxy2);
        }
        for (int by = by0 - 1; by >= 0; by--) {
            float dy = axdist(qy, by);
            float dxy2 = __fmaf_rn(dy, dy, dx2);
            if (dxy2 >= s2 + MARGIN_) break;
            dozrun(bx, by, dxy2);
        }
    };

    for (int bx = bx0; bx < GB_; bx++) {
        float dx = axdist(qx, bx);
        float dx2 = dx * dx;
        if (dx2 >= s2 + MARGIN_) break;
        docol(bx, dx2);
    }
    for (int bx = bx0 - 1; bx >= 0; bx--) {
        float dx = axdist(qx, bx);
        float dx2 = dx * dx;
        if (dx2 >= s2 + MARGIN_) break;
        docol(bx, dx2);
    }

    float w0 = __fdiv_rn(1.0f, s0);
    float w1 = __fdiv_rn(1.0f, s1);
    float w2 = __fdiv_rn(1.0f, s2);
    float ws = __fadd_rn(__fadd_rn(w0, w1), w2);
    size_t o = ((size_t)b * M_ + m) * 3;
    wout[o + 0] = __fdiv_rn(w0, ws);
    wout[o + 1] = __fdiv_rn(w1, ws);
    wout[o + 2] = __fdiv_rn(w2, ws);
    iout[o + 0] = i0; iout[o + 1] = i1; iout[o + 2] = i2;
}

// ---------------- fused Conv1d(k=1) + BN + ReLU GEMM (R4 version) ----------------
__global__ __launch_bounds__(256) void mlp_kernel(
    const float* __restrict__ X, const float* __restrict__ W,
    const float* __restrict__ bias, const float* __restrict__ gamma,
    const float* __restrict__ betap, const float* __restrict__ rmean,
    const float* __restrict__ rvar, float* __restrict__ Y,
    int K, int transposed)
{
    __shared__ float Ws[32][COUT_];
    __shared__ float Xs[32][64];
    const int tid = threadIdx.x;
    const int b   = blockIdx.y;
    const int n0  = blockIdx.x * 64;
    const float* Xb = X + (size_t)b * K * NIN_;

    ull acc2[4][4];
#pragma unroll
    for (int p = 0; p < 4; p++)
#pragma unroll
        for (int j = 0; j < 4; j++) acc2[p][j] = 0ull;

    const int rg    = tid >> 4;
    const int cg    = tid & 15;
    const int cout0 = rg * 8;
    const int nl    = cg * 4;

    for (int k0 = 0; k0 < K; k0 += 32) {
#pragma unroll
        for (int l = 0; l < 4; l++) {
            int idx = tid + l * 256;
            int co  = idx & 127;
            int kq  = idx >> 7;
            float4 w4 = *(const float4*)(W + (size_t)co * K + k0 + kq * 4);
            Ws[kq * 4 + 0][co] = w4.x;
            Ws[kq * 4 + 1][co] = w4.y;
            Ws[kq * 4 + 2][co] = w4.z;
            Ws[kq * 4 + 3][co] = w4.w;
        }
#pragma unroll
        for (int l = 0; l < 2; l++) {
            int idx = tid + l * 256;
            int nq  = idx & 15;
            int kk  = idx >> 4;
            *(float4*)&Xs[kk][nq * 4] =
                *(const float4*)(Xb + (size_t)(k0 + kk) * NIN_ + n0 + nq * 4);
        }
        __syncthreads();
#pragma unroll
        for (int k = 0; k < 32; k++) {
            ull ap[4];
#pragma unroll
            for (int p = 0; p < 4; p++)
                ap[p] = *(const ull*)&Ws[k][cout0 + 2 * p];
            float4 xb = *(const float4*)&Xs[k][nl];
            ull xd[4];
            xd[0] = pack2(xb.x, xb.x);
            xd[1] = pack2(xb.y, xb.y);
            xd[2] = pack2(xb.z, xb.z);
            xd[3] = pack2(xb.w, xb.w);
#pragma unroll
            for (int p = 0; p < 4; p++)
#pragma unroll
                for (int j = 0; j < 4; j++)
                    acc2[p][j] = fma2(ap[p], xd[j], acc2[p][j]);
        }
        __syncthreads();
    }

    float acc[8][4];
#pragma unroll
    for (int p = 0; p < 4; p++)
#pragma unroll
        for (int j = 0; j < 4; j++)
            unpack2(acc[2 * p][j], acc[2 * p + 1][j], acc2[p][j]);

    float sc[8], shf[8];
#pragma unroll
    for (int i = 0; i < 8; i++) {
        int c = cout0 + i;
        float s = gamma[c] / sqrtf(rvar[c] + 1e-5f);
        sc[i]  = s;
        shf[i] = betap[c] + (bias[c] - rmean[c]) * s;
    }

    if (!transposed) {
#pragma unroll
        for (int i = 0; i < 8; i++) {
            float4 v;
            v.x = fmaxf(__fmaf_rn(acc[i][0], sc[i], shf[i]), 0.f);
            v.y = fmaxf(__fmaf_rn(acc[i][1], sc[i], shf[i]), 0.f);
            v.z = fmaxf(__fmaf_rn(acc[i][2], sc[i], shf[i]), 0.f);
            v.w = fmaxf(__fmaf_rn(acc[i][3], sc[i], shf[i]), 0.f);
            *(float4*)(Y + ((size_t)b * COUT_ + cout0 + i) * NIN_ + n0 + nl) = v;
        }
    } else {
#pragma unroll
        for (int j = 0; j < 4; j++) {
            float v[8];
#pragma unroll
            for (int i = 0; i < 8; i++)
                v[i] = fmaxf(__fmaf_rn(acc[i][j], sc[i], shf[i]), 0.f);
            float* p = Y + ((size_t)b * NIN_ + n0 + nl + j) * COUT_ + cout0;
            *(float4*)(p)     = make_float4(v[0], v[1], v[2], v[3]);
            *(float4*)(p + 4) = make_float4(v[4], v[5], v[6], v[7]);
        }
    }
}

// ---------------- gather + weighted interpolation ----------------
__global__ __launch_bounds__(128) void interp_kernel(
    const float* __restrict__ featT, const float* __restrict__ wv,
    const int* __restrict__ iv, float* __restrict__ out)
{
    __shared__ float sacc[64][COUT_ + 1];
    __shared__ float sw[64 * 3];
    __shared__ int   si[64 * 3];
    const int tid = threadIdx.x;
    const int b   = blockIdx.y;
    const int m0  = blockIdx.x * 64;
    const size_t base = ((size_t)b * M_ + m0) * 3;

    for (int l = tid; l < 192; l += 128) {
        sw[l] = wv[base + l];
        si[l] = iv[base + l];
    }
    __syncthreads();

    const float* fb = featT + (size_t)b * NIN_ * COUT_;
    const int c = tid;
#pragma unroll 2
    for (int qq = 0; qq < 64; qq++) {
        float w0 = sw[qq * 3], w1 = sw[qq * 3 + 1], w2 = sw[qq * 3 + 2];
        const float* f0 = fb + (size_t)si[qq * 3]     * COUT_;
        const float* f1 = fb + (size_t)si[qq * 3 + 1] * COUT_;
        const float* f2 = fb + (size_t)si[qq * 3 + 2] * COUT_;
        sacc[qq][c] = __fmaf_rn(w2, f2[c],
                      __fmaf_rn(w1, f1[c], __fmul_rn(w0, f0[c])));
    }
    __syncthreads();

#pragma unroll
    for (int cc = 0; cc < COUT_; cc += 2) {
        int ci = cc + (tid >> 6);
        int mi = tid & 63;
        out[((size_t)b * COUT_ + ci) * M_ + m0 + mi] = sacc[mi][ci];
    }
}

// ---------------- launch ----------------
extern "C" void kernel_launch(void* const* d_in, const int* in_sizes, int n_in,
                              void* d_out, int out_size)
{
    (void)in_sizes; (void)n_in; (void)out_size;
    const float* rgb    = (const float*)d_in[0];
    const float* xyzin  = (const float*)d_in[1];
    const float* xyzout = (const float*)d_in[2];
    const float* w1 = (const float*)d_in[3];
    const float* b1 = (const float*)d_in[4];
    const float* g1 = (const float*)d_in[5];
    const float* be1 = (const float*)d_in[6];
    const float* rm1 = (const float*)d_in[7];
    const float* rv1 = (const float*)d_in[8];
    const float* w2 = (const float*)d_in[9];
    const float* b2 = (const float*)d_in[10];
    const float* g2 = (const float*)d_in[11];
    const float* be2 = (const float*)d_in[12];
    const float* rm2 = (const float*)d_in[13];
    const float* rv2 = (const float*)d_in[14];
    const float* w3 = (const float*)d_in[15];
    const float* b3 = (const float*)d_in[16];
    const float* g3 = (const float*)d_in[17];
    const float* be3 = (const float*)d_in[18];
    const float* rm3 = (const float*)d_in[19];
    const float* rv3 = (const float*)d_in[20];
    float* out = (float*)d_out;

    float *bufA, *bufB, *featT, *wvp;
    int *ivp, *sidxp, *cstartp, *qordp;
    float4* sptsp;
    cudaGetSymbolAddress((void**)&bufA,    g_bufA);
    cudaGetSymbolAddress((void**)&bufB,    g_bufB);
    cudaGetSymbolAddress((void**)&featT,   g_featT);
    cudaGetSymbolAddress((void**)&wvp,     g_wv);
    cudaGetSymbolAddress((void**)&ivp,     g_iv);
    cudaGetSymbolAddress((void**)&sptsp,   g_spts);
    cudaGetSymbolAddress((void**)&sidxp,   g_sidx);
    cudaGetSymbolAddress((void**)&cstartp, g_cstart);
    cudaGetSymbolAddress((void**)&qordp,   g_qord);

    // spatial preprocessing
    sortpts_kernel<<<B_, 256>>>(xyzin, sptsp, sidxp, cstartp);
    sortq_kernel<<<B_, 256>>>(xyzout, qordp);

    // MLP chain
    dim3 gemm_grid(NIN_ / 64, B_);
    mlp_kernel<<<gemm_grid, 256>>>(rgb,  w1, b1, g1, be1, rm1, rv1, bufA,  CIN_,  0);
    mlp_kernel<<<gemm_grid, 256>>>(bufA, w2, b2, g2, be2, rm2, rv2, bufB,  COUT_, 0);
    mlp_kernel<<<gemm_grid, 256>>>(bufB, w3, b3, g3, be3, rm3, rv3, featT, COUT_, 1);

    // grid 3-NN
    cudaFuncSetAttribute(nn_kernel,
                         cudaFuncAttributeMaxDynamicSharedMemorySize, SMEM_NN_);
    dim3 nn_grid(M_ / 256, B_);
    nn_kernel<<<nn_grid, 256, SMEM_NN_>>>(sptsp, sidxp, cstartp, qordp,
                                          xyzout, wvp, ivp);

    // interpolation
    dim3 interp_grid(M_ / 64, B_);
    interp_kernel<<<interp_grid, 128>>>(featT, wvp, ivp, out);
}

// round 9
// speedup vs baseline: 1.5267x; 1.5267x over previous
#include <cuda_runtime.h>
#include <math.h>
#include <float.h>
#include <stdint.h>

#define B_    4
#define NIN_  4096
#define M_    16384
#define CIN_  256
#define COUT_ 128
#define NSEG_ 4
#define SEGC_ (NIN_ / NSEG_)   // 1024 candidates per segment

typedef unsigned long long ull;

// ---------------- f32x2 packed helpers ----------------
__device__ __forceinline__ ull pack2(float lo, float hi) {
    ull r; asm("mov.b64 %0,{%1,%2};" : "=l"(r) : "f"(lo), "f"(hi)); return r;
}
__device__ __forceinline__ void unpack2(float& lo, float& hi, ull v) {
    asm("mov.b64 {%0,%1},%2;" : "=f"(lo), "=f"(hi) : "l"(v));
}
__device__ __forceinline__ ull fma2(ull a, ull b, ull c) {
    ull d; asm("fma.rn.f32x2 %0,%1,%2,%3;" : "=l"(d) : "l"(a), "l"(b), "l"(c)); return d;
}
__device__ __forceinline__ ull mul2(ull a, ull b) {
    ull d; asm("mul.rn.f32x2 %0,%1,%2;" : "=l"(d) : "l"(a), "l"(b)); return d;
}
__device__ __forceinline__ ull add2(ull a, ull b) {
    ull d; asm("add.rn.f32x2 %0,%1,%2;" : "=l"(d) : "l"(a), "l"(b)); return d;
}

// ---------------- scratch ----------------
__device__ float g_bufA[B_ * COUT_ * NIN_];
__device__ float g_bufB[B_ * COUT_ * NIN_];
__device__ float g_featT[B_ * NIN_ * COUT_];
__device__ float g_pval[B_ * NSEG_ * M_ * 3];
__device__ int   g_pidx[B_ * NSEG_ * M_ * 3];

// ---------------- fused Conv1d(k=1) + BN + ReLU GEMM (R4 version) ----------------
__global__ __launch_bounds__(256) void mlp_kernel(
    const float* __restrict__ X, const float* __restrict__ W,
    const float* __restrict__ bias, const float* __restrict__ gamma,
    const float* __restrict__ betap, const float* __restrict__ rmean,
    const float* __restrict__ rvar, float* __restrict__ Y,
    int K, int transposed)
{
    __shared__ float Ws[32][COUT_];
    __shared__ float Xs[32][64];
    const int tid = threadIdx.x;
    const int b   = blockIdx.y;
    const int n0  = blockIdx.x * 64;
    const float* Xb = X + (size_t)b * K * NIN_;

    ull acc2[4][4];
#pragma unroll
    for (int p = 0; p < 4; p++)
#pragma unroll
        for (int j = 0; j < 4; j++) acc2[p][j] = 0ull;

    const int rg    = tid >> 4;
    const int cg    = tid & 15;
    const int cout0 = rg * 8;
    const int nl    = cg * 4;

    for (int k0 = 0; k0 < K; k0 += 32) {
#pragma unroll
        for (int l = 0; l < 4; l++) {
            int idx = tid + l * 256;
            int co  = idx & 127;
            int kq  = idx >> 7;
            float4 w4 = *(const float4*)(W + (size_t)co * K + k0 + kq * 4);
            Ws[kq * 4 + 0][co] = w4.x;
            Ws[kq * 4 + 1][co] = w4.y;
            Ws[kq * 4 + 2][co] = w4.z;
            Ws[kq * 4 + 3][co] = w4.w;
        }
#pragma unroll
        for (int l = 0; l < 2; l++) {
            int idx = tid + l * 256;
            int nq  = idx & 15;
            int kk  = idx >> 4;
            *(float4*)&Xs[kk][nq * 4] =
                *(const float4*)(Xb + (size_t)(k0 + kk) * NIN_ + n0 + nq * 4);
        }
        __syncthreads();
#pragma unroll
        for (int k = 0; k < 32; k++) {
            ull ap[4];
#pragma unroll
            for (int p = 0; p < 4; p++)
                ap[p] = *(const ull*)&Ws[k][cout0 + 2 * p];
            float4 xb = *(const float4*)&Xs[k][nl];
            ull xd[4];
            xd[0] = pack2(xb.x, xb.x);
            xd[1] = pack2(xb.y, xb.y);
            xd[2] = pack2(xb.z, xb.z);
            xd[3] = pack2(xb.w, xb.w);
#pragma unroll
            for (int p = 0; p < 4; p++)
#pragma unroll
                for (int j = 0; j < 4; j++)
                    acc2[p][j] = fma2(ap[p], xd[j], acc2[p][j]);
        }
        __syncthreads();
    }

    float acc[8][4];
#pragma unroll
    for (int p = 0; p < 4; p++)
#pragma unroll
        for (int j = 0; j < 4; j++)
            unpack2(acc[2 * p][j], acc[2 * p + 1][j], acc2[p][j]);

    float sc[8], shf[8];
#pragma unroll
    for (int i = 0; i < 8; i++) {
        int c = cout0 + i;
        float s = gamma[c] / sqrtf(rvar[c] + 1e-5f);
        sc[i]  = s;
        shf[i] = betap[c] + (bias[c] - rmean[c]) * s;
    }

    if (!transposed) {
#pragma unroll
        for (int i = 0; i < 8; i++) {
            float4 v;
            v.x = fmaxf(__fmaf_rn(acc[i][0], sc[i], shf[i]), 0.f);
            v.y = fmaxf(__fmaf_rn(acc[i][1], sc[i], shf[i]), 0.f);
            v.z = fmaxf(__fmaf_rn(acc[i][2], sc[i], shf[i]), 0.f);
            v.w = fmaxf(__fmaf_rn(acc[i][3], sc[i], shf[i]), 0.f);
            *(float4*)(Y + ((size_t)b * COUT_ + cout0 + i) * NIN_ + n0 + nl) = v;
        }
    } else {
#pragma unroll
        for (int j = 0; j < 4; j++) {
            float v[8];
#pragma unroll
            for (int i = 0; i < 8; i++)
                v[i] = fmaxf(__fmaf_rn(acc[i][j], sc[i], shf[i]), 0.f);
            float* p = Y + ((size_t)b * NIN_ + n0 + nl + j) * COUT_ + cout0;
            *(float4*)(p)     = make_float4(v[0], v[1], v[2], v[3]);
            *(float4*)(p + 4) = make_float4(v[4], v[5], v[6], v[7]);
        }
    }
}

// ---------------- segmented exact top-3 scan (R4 best: NSEG=4, Q=2) ----------------
#define INSERT3(d_, j_, s0_, s1_, s2_, i0_, i1_, i2_)                      \
    if (d_ < s2_) {                                                        \
        if (d_ < s1_) {                                                    \
            s2_ = s1_; i2_ = i1_;                                          \
            if (d_ < s0_) { s1_ = s0_; i1_ = i0_; s0_ = d_; i0_ = j_; }    \
            else          { s1_ = d_;  i1_ = j_; }                         \
        } else { s2_ = d_; i2_ = j_; }                                     \
    }

__global__ __launch_bounds__(256) void scan_kernel(
    const float* __restrict__ xyzin, const float* __restrict__ xyzout,
    float* __restrict__ pval, int* __restrict__ pidx)
{
    __shared__ __align__(16) float xs[SEGC_];
    __shared__ __align__(16) float ys[SEGC_];
    __shared__ __align__(16) float zs[SEGC_];
    __shared__ __align__(16) float ss[SEGC_];

    const int tid = threadIdx.x;
    const int seg = blockIdx.y;
    const int b   = blockIdx.z;
    const int jbase = seg * SEGC_;
    const float* pin = xyzin + ((size_t)b * NIN_ + jbase) * 3;

    for (int j = tid; j < SEGC_; j += 256) {
        float x = pin[j * 3 + 0];
        float y = pin[j * 3 + 1];
        float z = pin[j * 3 + 2];
        xs[j] = x; ys[j] = y; zs[j] = z;
        ss[j] = __fadd_rn(__fadd_rn(__fmul_rn(x, x), __fmul_rn(y, y)),
                          __fmul_rn(z, z));
    }
    __syncthreads();

    const int m0 = blockIdx.x * 512 + tid;
    const int m1 = m0 + 256;

    const float* q0 = xyzout + ((size_t)b * M_ + m0) * 3;
    const float* q1 = xyzout + ((size_t)b * M_ + m1) * 3;
    float q0x = q0[0], q0y = q0[1], q0z = q0[2];
    float q1x = q1[0], q1y = q1[1], q1z = q1[2];
    float q0n = __fadd_rn(__fadd_rn(__fmul_rn(q0x, q0x), __fmul_rn(q0y, q0y)),
                          __fmul_rn(q0z, q0z));
    float q1n = __fadd_rn(__fadd_rn(__fmul_rn(q1x, q1x), __fmul_rn(q1y, q1y)),
                          __fmul_rn(q1z, q1z));

    const ull qx20 = pack2(q0x, q0x), qy20 = pack2(q0y, q0y);
    const ull qz20 = pack2(q0z, q0z), qn20 = pack2(q0n, q0n);
    const ull qx21 = pack2(q1x, q1x), qy21 = pack2(q1y, q1y);
    const ull qz21 = pack2(q1z, q1z), qn21 = pack2(q1n, q1n);
    const ull n22  = pack2(-2.0f, -2.0f);

    float a_s0 = FLT_MAX, a_s1 = FLT_MAX, a_s2 = FLT_MAX;
    float b_s0 = FLT_MAX, b_s1 = FLT_MAX, b_s2 = FLT_MAX;
    int a_i0 = 0, a_i1 = 0, a_i2 = 0;
    int b_i0 = 0, b_i1 = 0, b_i2 = 0;

    const ulonglong2* xs4 = (const ulonglong2*)xs;
    const ulonglong2* ys4 = (const ulonglong2*)ys;
    const ulonglong2* zs4 = (const ulonglong2*)zs;
    const ulonglong2* ss4 = (const ulonglong2*)ss;

#pragma unroll 2
    for (int jq = 0; jq < SEGC_ / 4; jq++) {
        ulonglong2 xq = xs4[jq], yq = ys4[jq], zq = zs4[jq], sq = ss4[jq];
#pragma unroll
        for (int p = 0; p < 2; p++) {
            ull xp = p ? xq.y : xq.x;
            ull yp = p ? yq.y : yq.x;
            ull zp = p ? zq.y : zq.x;
            ull sp = p ? sq.y : sq.x;
            int j = jbase + 4 * jq + 2 * p;
            // query 0
            {
                ull dot = fma2(qz20, zp, fma2(qy20, yp, mul2(qx20, xp)));
                ull d2  = fma2(n22, dot, add2(qn20, sp));
                float dlo, dhi; unpack2(dlo, dhi, d2);
                if (__builtin_expect(fminf(dlo, dhi) < a_s2, 0)) {
                    float cl = (dlo < 0.0f) ? 1e-7f : dlo;
                    float ch = (dhi < 0.0f) ? 1e-7f : dhi;
                    INSERT3(cl, j,     a_s0, a_s1, a_s2, a_i0, a_i1, a_i2);
                    INSERT3(ch, j + 1, a_s0, a_s1, a_s2, a_i0, a_i1, a_i2);
                }
            }
            // query 1
            {
                ull dot = fma2(qz21, zp, fma2(qy21, yp, mul2(qx21, xp)));
                ull d2  = fma2(n22, dot, add2(qn21, sp));
                float dlo, dhi; unpack2(dlo, dhi, d2);
                if (__builtin_expect(fminf(dlo, dhi) < b_s2, 0)) {
                    float cl = (dlo < 0.0f) ? 1e-7f : dlo;
                    float ch = (dhi < 0.0f) ? 1e-7f : dhi;
                    INSERT3(cl, j,     b_s0, b_s1, b_s2, b_i0, b_i1, b_i2);
                    INSERT3(ch, j + 1, b_s0, b_s1, b_s2, b_i0, b_i1, b_i2);
                }
            }
        }
    }

    {
        size_t o = (((size_t)b * NSEG_ + seg) * M_ + m0) * 3;
        pval[o + 0] = a_s0; pval[o + 1] = a_s1; pval[o + 2] = a_s2;
        pidx[o + 0] = a_i0; pidx[o + 1] = a_i1; pidx[o + 2] = a_i2;
    }
    {
        size_t o = (((size_t)b * NSEG_ + seg) * M_ + m1) * 3;
        pval[o + 0] = b_s0; pval[o + 1] = b_s1; pval[o + 2] = b_s2;
        pidx[o + 0] = b_i0; pidx[o + 1] = b_i1; pidx[o + 2] = b_i2;
    }
}

// ---------------- fused merge + gather + weighted interpolation ----------------
// Threads 0..63 each merge one query's NSEG_*3 partials (lexicographic (val,idx)
// == stable top_k, same arithmetic as before -> bitwise identical output),
// then all 128 threads do the feature gather + transposed write.
__global__ __launch_bounds__(128) void interp_kernel(
    const float* __restrict__ featT,
    const float* __restrict__ pval, const int* __restrict__ pidx,
    float* __restrict__ out)
{
    __shared__ float sacc[64][COUT_ + 1];
    __shared__ float sw[64 * 3];
    __shared__ int   si[64 * 3];
    const int tid = threadIdx.x;
    const int b   = blockIdx.y;
    const int m0  = blockIdx.x * 64;

    if (tid < 64) {
        const int m = m0 + tid;
        float v[NSEG_ * 3];
        int   ix[NSEG_ * 3];
#pragma unroll
        for (int s = 0; s < NSEG_; s++) {
            size_t o = (((size_t)b * NSEG_ + s) * M_ + m) * 3;
#pragma unroll
            for (int k = 0; k < 3; k++) {
                v[s * 3 + k]  = pval[o + k];
                ix[s * 3 + k] = pidx[o + k];
            }
        }
        float rs[3]; int ri[3];
#pragma unroll
        for (int k = 0; k < 3; k++) {
            int best = 0;
#pragma unroll
            for (int t = 1; t < NSEG_ * 3; t++) {
                bool better = (v[t] < v[best]) ||
                              (v[t] == v[best] && ix[t] < ix[best]);
                if (better) best = t;
            }
            rs[k] = v[best]; ri[k] = ix[best];
            v[best] = FLT_MAX; ix[best] = 0x7FFFFFFF;
        }
        float w0 = __fdiv_rn(1.0f, rs[0]);
        float w1 = __fdiv_rn(1.0f, rs[1]);
        float w2 = __fdiv_rn(1.0f, rs[2]);
        float wsum = __fadd_rn(__fadd_rn(w0, w1), w2);
        sw[tid * 3 + 0] = __fdiv_rn(w0, wsum);
        sw[tid * 3 + 1] = __fdiv_rn(w1, wsum);
        sw[tid * 3 + 2] = __fdiv_rn(w2, wsum);
        si[tid * 3 + 0] = ri[0];
        si[tid * 3 + 1] = ri[1];
        si[tid * 3 + 2] = ri[2];
    }
    __syncthreads();

    const float* fb = featT + (size_t)b * NIN_ * COUT_;
    const int c = tid;
#pragma unroll 2
    for (int qq = 0; qq < 64; qq++) {
        float w0 = sw[qq * 3], w1 = sw[qq * 3 + 1], w2 = sw[qq * 3 + 2];
        const float* f0 = fb + (size_t)si[qq * 3]     * COUT_;
        const float* f1 = fb + (size_t)si[qq * 3 + 1] * COUT_;
        const float* f2 = fb + (size_t)si[qq * 3 + 2] * COUT_;
        sacc[qq][c] = __fmaf_rn(w2, f2[c],
                      __fmaf_rn(w1, f1[c], __fmul_rn(w0, f0[c])));
    }
    __syncthreads();

#pragma unroll
    for (int cc = 0; cc < COUT_; cc += 2) {
        int ci = cc + (tid >> 6);
        int mi = tid & 63;
        out[((size_t)b * COUT_ + ci) * M_ + m0 + mi] = sacc[mi][ci];
    }
}

// ---------------- launch (stream-forked: scan || mlp chain) ----------------
extern "C" void kernel_launch(void* const* d_in, const int* in_sizes, int n_in,
                              void* d_out, int out_size)
{
    (void)in_sizes; (void)n_in; (void)out_size;
    const float* rgb    = (const float*)d_in[0];
    const float* xyzin  = (const float*)d_in[1];
    const float* xyzout = (const float*)d_in[2];
    const float* w1 = (const float*)d_in[3];
    const float* b1 = (const float*)d_in[4];
    const float* g1 = (const float*)d_in[5];
    const float* be1 = (const float*)d_in[6];
    const float* rm1 = (const float*)d_in[7];
    const float* rv1 = (const float*)d_in[8];
    const float* w2 = (const float*)d_in[9];
    const float* b2 = (const float*)d_in[10];
    const float* g2 = (const float*)d_in[11];
    const float* be2 = (const float*)d_in[12];
    const float* rm2 = (const float*)d_in[13];
    const float* rv2 = (const float*)d_in[14];
    const float* w3 = (const float*)d_in[15];
    const float* b3 = (const float*)d_in[16];
    const float* g3 = (const float*)d_in[17];
    const float* be3 = (const float*)d_in[18];
    const float* rm3 = (const float*)d_in[19];
    const float* rv3 = (const float*)d_in[20];
    float* out = (float*)d_out;

    float *bufA, *bufB, *featT, *pvp;
    int *pip;
    cudaGetSymbolAddress((void**)&bufA,  g_bufA);
    cudaGetSymbolAddress((void**)&bufB,  g_bufB);
    cudaGetSymbolAddress((void**)&featT, g_featT);
    cudaGetSymbolAddress((void**)&pvp,   g_pval);
    cudaGetSymbolAddress((void**)&pip,   g_pidx);

    // lazily created side stream + events (created outside capture on the
    // correctness call; reused, never destroyed)
    static cudaStream_t s_side = nullptr;
    static cudaEvent_t  ev_fork = nullptr, ev_join = nullptr;
    if (s_side == nullptr) {
        cudaStreamCreateWithFlags(&s_side, cudaStreamNonBlocking);
        cudaEventCreateWithFlags(&ev_fork, cudaEventDisableTiming);
        cudaEventCreateWithFlags(&ev_join, cudaEventDisableTiming);
    }

    // fork: side stream joins the (possibly capturing) default stream
    cudaEventRecord(ev_fork, 0);
    cudaStreamWaitEvent(s_side, ev_fork, 0);

    // side stream: 3-NN scan
    dim3 scan_grid(M_ / 512, NSEG_, B_);
    scan_kernel<<<scan_grid, 256, 0, s_side>>>(xyzin, xyzout, pvp, pip);
    cudaEventRecord(ev_join, s_side);

    // default stream: MLP chain (concurrent with scan)
    dim3 gemm_grid(NIN_ / 64, B_);
    mlp_kernel<<<gemm_grid, 256>>>(rgb,  w1, b1, g1, be1, rm1, rv1, bufA,  CIN_,  0);
    mlp_kernel<<<gemm_grid, 256>>>(bufA, w2, b2, g2, be2, rm2, rv2, bufB,  COUT_, 0);
    mlp_kernel<<<gemm_grid, 256>>>(bufB, w3, b3, g3, be3, rm3, rv3, featT, COUT_, 1);

    // join: interp needs featT (default stream) + partials (side stream)
    cudaStreamWaitEvent(0, ev_join, 0);

    dim3 interp_grid(M_ / 64, B_);
    interp_kernel<<<interp_grid, 128>>>(featT, pvp, pip, out);
}